// round 7
// baseline (speedup 1.0000x reference)
#include <cuda_runtime.h>

#define IMG_H 512
#define IMG_W 512

__constant__ float c_k[9];
__constant__ float c_w1[10];
__constant__ float c_b1[10];
__constant__ float c_w2[10];

// Pointwise chain (identical math to the validated R3 kernel):
// gaussian -> MLP(1->10 relu ->1) -> sigmoid -> -0.5
__device__ __forceinline__ float act(float v) {
    float t = v - 1.0f;
    float g = __expf(-t * t);
    float s = 0.0f;
#pragma unroll
    for (int j = 0; j < 10; ++j) {
        float h = fmaf(c_w1[j], g, c_b1[j]);
        s = fmaf(c_w2[j], fmaxf(h, 0.0f), s);
    }
    float e = __expf(-s);
    float sig = __fdividef(1.0f, 1.0f + e);
    return sig - 0.5f;
}

// One NCA step. blockDim=(32,4); each thread: 4 cols (float4) x T rows.
// 4-row register window, loads issued 2 rows ahead of use; halos via shuffle.
template <int T>
__global__ __launch_bounds__(128, 7) void step_kernel(const float* __restrict__ in,
                                                      float* __restrict__ out) {
    const int tx = threadIdx.x;                       // 0..31 (one warp per ty)
    const int c0 = (blockIdx.x * 32 + tx) * 4;
    const int b  = blockIdx.z;
    const int y0 = (blockIdx.y * blockDim.y + threadIdx.y) * T;

    const float* img  = in  + (size_t)b * (IMG_H * IMG_W);
    float*       oimg = out + (size_t)b * (IMG_H * IMG_W);

    float win[4][6];   // 4-row sliding window: [c0-1, c0..c0+3, c0+4]

    auto load_row = [&](int y, float* r) {
        if (y < 0 || y >= IMG_H) {
#pragma unroll
            for (int i = 0; i < 6; ++i) r[i] = 0.0f;
            return;
        }
        const float* p = img + y * IMG_W + c0;
        float4 v = *reinterpret_cast<const float4*>(p);
        // halos from neighbor lanes (warp spans a contiguous 128-col strip)
        float left  = __shfl_up_sync(0xffffffffu,  v.w, 1);
        float right = __shfl_down_sync(0xffffffffu, v.x, 1);
        if (tx == 0)  left  = (c0 > 0)         ? __ldg(p - 1) : 0.0f;
        if (tx == 31) right = (c0 + 4 < IMG_W) ? __ldg(p + 4) : 0.0f;
        r[0] = left;
        r[1] = v.x; r[2] = v.y; r[3] = v.z; r[4] = v.w;
        r[5] = right;
    };

    // prologue: rows y0-1, y0, y0+1 in buffers 0,1,2
    load_row(y0 - 1, win[0]);
    load_row(y0,     win[1]);
    load_row(y0 + 1, win[2]);

#pragma unroll
    for (int t = 0; t < T; ++t) {
        const int y = y0 + t;
        // prefetch row y+2 (consumed next iteration) before computing row y
        load_row(y + 2, win[(t + 3) & 3]);

        float* rm = win[(t + 0) & 3];
        float* rc = win[(t + 1) & 3];
        float* rp = win[(t + 2) & 3];

        float res[4];
#pragma unroll
        for (int i = 0; i < 4; ++i) {
            float v;
            v = c_k[0] * rm[i];
            v = fmaf(c_k[1], rm[i + 1], v);
            v = fmaf(c_k[2], rm[i + 2], v);
            v = fmaf(c_k[3], rc[i],     v);
            v = fmaf(c_k[4], rc[i + 1], v);
            v = fmaf(c_k[5], rc[i + 2], v);
            v = fmaf(c_k[6], rp[i],     v);
            v = fmaf(c_k[7], rp[i + 1], v);
            v = fmaf(c_k[8], rp[i + 2], v);
            res[i] = rc[i + 1] + act(v);    // residual update
        }
        float4 o;
        o.x = res[0]; o.y = res[1]; o.z = res[2]; o.w = res[3];
        *reinterpret_cast<float4*>(oimg + y * IMG_W + c0) = o;
    }
}

extern "C" void kernel_launch(void* const* d_in, const int* in_sizes, int n_in,
                              void* d_out, int out_size) {
    const float* x  = (const float*)d_in[0];
    const float* k  = (const float*)d_in[1];
    const float* w1 = (const float*)d_in[2];
    const float* b1 = (const float*)d_in[3];
    const float* w2 = (const float*)d_in[4];
    float* out = (float*)d_out;

    const int npix  = in_sizes[0];
    const int B     = npix / (IMG_H * IMG_W);
    const int steps = out_size / npix - 1;

    // Weights -> constant memory (device-to-device async copies: capturable)
    cudaMemcpyToSymbolAsync(c_k,  k,  9 * sizeof(float), 0, cudaMemcpyDeviceToDevice, 0);
    cudaMemcpyToSymbolAsync(c_w1, w1, 10 * sizeof(float), 0, cudaMemcpyDeviceToDevice, 0);
    cudaMemcpyToSymbolAsync(c_b1, b1, 10 * sizeof(float), 0, cudaMemcpyDeviceToDevice, 0);
    cudaMemcpyToSymbolAsync(c_w2, w2, 10 * sizeof(float), 0, cudaMemcpyDeviceToDevice, 0);

    // Slice 0 of the output is the initial state
    cudaMemcpyAsync(out, x, (size_t)npix * sizeof(float), cudaMemcpyDeviceToDevice, 0);

    constexpr int T = 8;
    dim3 blk(32, 4, 1);
    dim3 grd(IMG_W / (32 * 4), IMG_H / (4 * T), B);   // (4, 16, B) = 1024 CTAs

    for (int s = 0; s < steps; ++s) {
        const float* src = out + (size_t)s       * npix;
        float*       dst = out + (size_t)(s + 1) * npix;
        step_kernel<T><<<grd, blk>>>(src, dst);
    }
}

// round 9
// speedup vs baseline: 1.2587x; 1.2587x over previous
#include <cuda_runtime.h>

#define IMG_H 512
#define IMG_W 512

__constant__ float c_k[9];
// derived pointwise params: [0]=a, [1]=b, [2..11]=g_j, [12..21]=d_j
__constant__ float c_p[22];

__device__ float d_scratch[22];

// Build derived params: s(g) = a*g + b + sum_j d_j * |g - g_j|
//  (exact rewrite of sum_j w2_j * relu(w1_j*g + b1_j) via relu(x)=(x+|x|)/2)
__global__ void prep_kernel(const float* __restrict__ w1,
                            const float* __restrict__ b1,
                            const float* __restrict__ w2) {
    if (threadIdx.x != 0) return;
    float a = 0.0f, b = 0.0f;
    for (int j = 0; j < 10; ++j) {
        float W1 = w1[j], B1 = b1[j], W2 = w2[j];
        a += 0.5f * W2 * W1;
        b += 0.5f * W2 * B1;
        if (fabsf(W1) > 1e-30f) {
            d_scratch[2 + j]  = -B1 / W1;            // g_j (precise divide)
            d_scratch[12 + j] = 0.5f * W2 * fabsf(W1);
        } else {
            d_scratch[2 + j]  = 0.0f;
            d_scratch[12 + j] = 0.0f;
            b += 0.5f * W2 * fabsf(B1);              // w2*relu(b1) residue
        }
    }
    d_scratch[0] = a;
    d_scratch[1] = b;
}

// Pointwise chain: gaussian -> abs-form MLP -> sigmoid - 0.5
__device__ __forceinline__ float act(float v) {
    float t = v - 1.0f;
    float g = __expf(-t * t);
    float s = fmaf(c_p[0], g, c_p[1]);
#pragma unroll
    for (int j = 0; j < 10; ++j) {
        float u = g - c_p[2 + j];
        s = fmaf(c_p[12 + j], fabsf(u), s);   // |u| is a free operand modifier
    }
    float e = __expf(-s);
    float r;
    asm("rcp.approx.f32 %0, %1;" : "=f"(r) : "f"(1.0f + e));
    return r - 0.5f;                           // sigmoid(s) - 0.5
}

// One NCA step (structure identical to the validated 177us kernel):
// blockDim=(32,8); each thread: 4 cols (float4) x T rows, 3-row sliding window.
template <int T>
__global__ __launch_bounds__(256) void step_kernel(const float* __restrict__ in,
                                                   float* __restrict__ out) {
    const int tx = threadIdx.x;                       // 0..31
    const int c0 = (blockIdx.x * 32 + tx) * 4;
    const int b  = blockIdx.z;
    const int y0 = (blockIdx.y * blockDim.y + threadIdx.y) * T;

    const float* img  = in  + (size_t)b * (IMG_H * IMG_W);
    float*       oimg = out + (size_t)b * (IMG_H * IMG_W);

    float win[3][6];   // 3-row sliding window, 6 cols: [c0-1, c0..c0+3, c0+4]

    auto load_row = [&](int y, float* r) {
#pragma unroll
        for (int i = 0; i < 6; ++i) r[i] = 0.0f;
        if (y >= 0 && y < IMG_H) {
            const float* p = img + y * IMG_W + c0;
            float4 v = *reinterpret_cast<const float4*>(p);
            r[1] = v.x; r[2] = v.y; r[3] = v.z; r[4] = v.w;
            if (c0 > 0)           r[0] = __ldg(p - 1);
            if (c0 + 4 < IMG_W)   r[5] = __ldg(p + 4);
        }
    };

    load_row(y0 - 1, win[0]);
    load_row(y0,     win[1]);

#pragma unroll
    for (int t = 0; t < T; ++t) {
        const int y = y0 + t;
        float* rm = win[(t + 0) % 3];   // row y-1
        float* rc = win[(t + 1) % 3];   // row y
        float* rp = win[(t + 2) % 3];   // row y+1
        load_row(y + 1, rp);

        float res[4];
#pragma unroll
        for (int i = 0; i < 4; ++i) {
            float v;
            v = c_k[0] * rm[i];
            v = fmaf(c_k[1], rm[i + 1], v);
            v = fmaf(c_k[2], rm[i + 2], v);
            v = fmaf(c_k[3], rc[i],     v);
            v = fmaf(c_k[4], rc[i + 1], v);
            v = fmaf(c_k[5], rc[i + 2], v);
            v = fmaf(c_k[6], rp[i],     v);
            v = fmaf(c_k[7], rp[i + 1], v);
            v = fmaf(c_k[8], rp[i + 2], v);
            res[i] = rc[i + 1] + act(v);   // residual update
        }
        float4 o;
        o.x = res[0]; o.y = res[1]; o.z = res[2]; o.w = res[3];
        *reinterpret_cast<float4*>(oimg + y * IMG_W + c0) = o;
    }
}

extern "C" void kernel_launch(void* const* d_in, const int* in_sizes, int n_in,
                              void* d_out, int out_size) {
    const float* x  = (const float*)d_in[0];
    const float* k  = (const float*)d_in[1];
    const float* w1 = (const float*)d_in[2];
    const float* b1 = (const float*)d_in[3];
    const float* w2 = (const float*)d_in[4];
    float* out = (float*)d_out;

    const int npix  = in_sizes[0];
    const int B     = npix / (IMG_H * IMG_W);
    const int steps = out_size / npix - 1;

    cudaMemcpyToSymbolAsync(c_k, k, 9 * sizeof(float), 0, cudaMemcpyDeviceToDevice, 0);

    // Build derived pointwise params on device, then stage into constant memory.
    // NOTE: use the REAL device address of d_scratch (cudaGetSymbolAddress),
    // not the host shadow symbol (that was the R6 bug).
    prep_kernel<<<1, 32>>>(w1, b1, w2);
    void* scratch_dev = nullptr;
    cudaGetSymbolAddress(&scratch_dev, d_scratch);
    cudaMemcpyToSymbolAsync(c_p, scratch_dev, 22 * sizeof(float), 0,
                            cudaMemcpyDeviceToDevice, 0);

    // Slice 0 of the output is the initial state
    cudaMemcpyAsync(out, x, (size_t)npix * sizeof(float), cudaMemcpyDeviceToDevice, 0);

    constexpr int T = 4;
    dim3 blk(32, 8, 1);
    dim3 grd(IMG_W / (32 * 4), IMG_H / (8 * T), B);   // (4, 16, B)

    for (int s = 0; s < steps; ++s) {
        const float* src = out + (size_t)s       * npix;
        float*       dst = out + (size_t)(s + 1) * npix;
        step_kernel<T><<<grd, blk>>>(src, dst);
    }
}

// round 10
// speedup vs baseline: 1.3369x; 1.0621x over previous
#include <cuda_runtime.h>

#define IMG_H 512
#define IMG_W 512

typedef unsigned long long u64;

__constant__ u64   c_k2[9];    // conv weights packed {k,k}
__constant__ float c_pw[22];   // [0]=a, [1]=b, [2..11]=g_j, [12..21]=d_j (padded)
__constant__ int   c_cnt;      // interior-unit count (even, 0..10)

__device__ u64   d_k2s[9];
__device__ float d_pws[22];
__device__ int   d_cnts;

__device__ __forceinline__ u64 pack2(float lo, float hi) {
    u64 r; asm("mov.b64 %0, {%1, %2};" : "=l"(r) : "f"(lo), "f"(hi)); return r;
}
__device__ __forceinline__ void unpack2(u64 v, float& lo, float& hi) {
    asm("mov.b64 {%0, %1}, %2;" : "=f"(lo), "=f"(hi) : "l"(v));
}
__device__ __forceinline__ u64 ffma2(u64 a, u64 b, u64 c) {
    u64 r; asm("fma.rn.f32x2 %0, %1, %2, %3;" : "=l"(r) : "l"(a), "l"(b), "l"(c)); return r;
}
__device__ __forceinline__ u64 fmul2(u64 a, u64 b) {
    u64 r; asm("mul.rn.f32x2 %0, %1, %2;" : "=l"(r) : "l"(a), "l"(b)); return r;
}

// Fold units whose ReLU knot lies outside g-domain [0,1] into the affine part.
// s(g) = a*g + b + sum_{j<cnt} d_j*|g - g_j|   (exact rewrite; g = exp(-(v-1)^2))
__global__ void prep_kernel(const float* __restrict__ k,
                            const float* __restrict__ w1,
                            const float* __restrict__ b1,
                            const float* __restrict__ w2) {
    if (threadIdx.x != 0 || blockIdx.x != 0) return;
    for (int i = 0; i < 9; ++i) d_k2s[i] = pack2(k[i], k[i]);
    float a = 0.0f, b = 0.0f;
    int cnt = 0;
    float gj[10], dj[10];
    for (int j = 0; j < 10; ++j) {
        float W1 = w1[j], B1 = b1[j], W2 = w2[j];
        a += 0.5f * W2 * W1;
        b += 0.5f * W2 * B1;
        bool always_on  = (B1 >= 0.0f) && (W1 + B1 >= 0.0f);
        bool always_off = (B1 <= 0.0f) && (W1 + B1 <= 0.0f);
        if (always_on) {            // |x| = x on [0,1]
            a += 0.5f * W2 * W1;
            b += 0.5f * W2 * B1;
        } else if (always_off) {    // |x| = -x on [0,1]
            a -= 0.5f * W2 * W1;
            b -= 0.5f * W2 * B1;
        } else {                    // knot inside (0,1): keep abs term
            gj[cnt] = -B1 / W1;
            dj[cnt] = 0.5f * W2 * fabsf(W1);
            cnt++;
        }
    }
    if (cnt & 1) { gj[cnt] = 0.0f; dj[cnt] = 0.0f; cnt++; }  // pad to even
    d_pws[0] = a; d_pws[1] = b;
    for (int j = 0; j < 10; ++j) {
        d_pws[2 + j]  = (j < cnt) ? gj[j] : 0.0f;
        d_pws[12 + j] = (j < cnt) ? dj[j] : 0.0f;
    }
    d_cnts = cnt;
}

#define L2E 1.4426950408889634f

template <int N>
__device__ __forceinline__ float act(float v) {
    // g = exp2(-L2E*(v-1)^2) expanded: q = (v*(-L2E) + 2L2E)*v - L2E  (2 fma)
    float q = fmaf(v, -L2E, 2.0f * L2E);
    q = fmaf(q, v, -L2E);
    float g; asm("ex2.approx.f32 %0, %1;" : "=f"(g) : "f"(q));
    float s = fmaf(c_pw[0], g, c_pw[1]);
#pragma unroll
    for (int j = 0; j < N; ++j)
        s = fmaf(c_pw[12 + j], fabsf(g - c_pw[2 + j]), s);   // |.| free modifier
    float e; float m = s * -L2E;
    asm("ex2.approx.f32 %0, %1;" : "=f"(e) : "f"(m));        // e = exp(-s)
    float r;
    asm("rcp.approx.f32 %0, %1;" : "=f"(r) : "f"(1.0f + e));
    return r - 0.5f;                                          // sigmoid(s) - 0.5
}

// Tile body: T rows x 4 cols per thread; rows held as 5 packed pairs {r_i, r_i+1}.
template <int T, int N>
__device__ __forceinline__ void run_tile(const float* __restrict__ img,
                                         float* __restrict__ oimg,
                                         int c0, int y0) {
    u64 win[3][5];

    auto load_row = [&](int y, u64* P) {
        if (y < 0 || y >= IMG_H) {
#pragma unroll
            for (int i = 0; i < 5; ++i) P[i] = 0ull;
            return;
        }
        const float* p = img + y * IMG_W + c0;
        float4 v = *reinterpret_cast<const float4*>(p);
        float l = (c0 > 0)         ? __ldg(p - 1) : 0.0f;
        float r = (c0 + 4 < IMG_W) ? __ldg(p + 4) : 0.0f;
        P[0] = pack2(l,   v.x);
        P[1] = pack2(v.x, v.y);
        P[2] = pack2(v.y, v.z);
        P[3] = pack2(v.z, v.w);
        P[4] = pack2(v.w, r);
    };

    load_row(y0 - 1, win[0]);
    load_row(y0,     win[1]);

#pragma unroll
    for (int t = 0; t < T; ++t) {
        const int y = y0 + t;
        u64* rm = win[(t + 0) % 3];
        u64* rc = win[(t + 1) % 3];
        u64* rp = win[(t + 2) % 3];
        load_row(y + 1, rp);

        // conv for pixel pairs (0,1) and (2,3): 18 packed FFMA
        u64 v01 = fmul2(c_k2[0], rm[0]);
        v01 = ffma2(c_k2[1], rm[1], v01);
        v01 = ffma2(c_k2[2], rm[2], v01);
        v01 = ffma2(c_k2[3], rc[0], v01);
        v01 = ffma2(c_k2[4], rc[1], v01);
        v01 = ffma2(c_k2[5], rc[2], v01);
        v01 = ffma2(c_k2[6], rp[0], v01);
        v01 = ffma2(c_k2[7], rp[1], v01);
        v01 = ffma2(c_k2[8], rp[2], v01);

        u64 v23 = fmul2(c_k2[0], rm[2]);
        v23 = ffma2(c_k2[1], rm[3], v23);
        v23 = ffma2(c_k2[2], rm[4], v23);
        v23 = ffma2(c_k2[3], rc[2], v23);
        v23 = ffma2(c_k2[4], rc[3], v23);
        v23 = ffma2(c_k2[5], rc[4], v23);
        v23 = ffma2(c_k2[6], rp[2], v23);
        v23 = ffma2(c_k2[7], rp[3], v23);
        v23 = ffma2(c_k2[8], rp[4], v23);

        float f0, f1, f2, f3;
        unpack2(v01, f0, f1);
        unpack2(v23, f2, f3);

        // residual centers: {r1,r2} = rc P1, {r3,r4} = rc P3
        float x0, x1, x2, x3;
        unpack2(rc[1], x0, x1);
        unpack2(rc[3], x2, x3);

        float4 o;
        o.x = x0 + act<N>(f0);
        o.y = x1 + act<N>(f1);
        o.z = x2 + act<N>(f2);
        o.w = x3 + act<N>(f3);
        *reinterpret_cast<float4*>(oimg + y * IMG_W + c0) = o;
    }
}

template <int T>
__global__ __launch_bounds__(256) void step_kernel(const float* __restrict__ in,
                                                   float* __restrict__ out) {
    const int tx = threadIdx.x;                       // 0..31
    const int c0 = (blockIdx.x * 32 + tx) * 4;
    const int b  = blockIdx.z;
    const int y0 = (blockIdx.y * blockDim.y + threadIdx.y) * T;

    const float* img  = in  + (size_t)b * (IMG_H * IMG_W);
    float*       oimg = out + (size_t)b * (IMG_H * IMG_W);

    const int n = c_cnt;                              // uniform dispatch
    if      (n == 0)  run_tile<T, 0 >(img, oimg, c0, y0);
    else if (n == 2)  run_tile<T, 2 >(img, oimg, c0, y0);
    else if (n == 4)  run_tile<T, 4 >(img, oimg, c0, y0);
    else if (n == 6)  run_tile<T, 6 >(img, oimg, c0, y0);
    else if (n == 8)  run_tile<T, 8 >(img, oimg, c0, y0);
    else              run_tile<T, 10>(img, oimg, c0, y0);
}

extern "C" void kernel_launch(void* const* d_in, const int* in_sizes, int n_in,
                              void* d_out, int out_size) {
    const float* x  = (const float*)d_in[0];
    const float* k  = (const float*)d_in[1];
    const float* w1 = (const float*)d_in[2];
    const float* b1 = (const float*)d_in[3];
    const float* w2 = (const float*)d_in[4];
    float* out = (float*)d_out;

    const int npix  = in_sizes[0];
    const int B     = npix / (IMG_H * IMG_W);
    const int steps = out_size / npix - 1;

    // Build derived params on device, then stage into constant memory
    // (real device addresses via cudaGetSymbolAddress — not host shadows).
    prep_kernel<<<1, 32>>>(k, w1, b1, w2);
    void *pk2 = nullptr, *ppw = nullptr, *pcnt = nullptr;
    cudaGetSymbolAddress(&pk2,  d_k2s);
    cudaGetSymbolAddress(&ppw,  d_pws);
    cudaGetSymbolAddress(&pcnt, d_cnts);
    cudaMemcpyToSymbolAsync(c_k2,  pk2,  9 * sizeof(u64),    0, cudaMemcpyDeviceToDevice, 0);
    cudaMemcpyToSymbolAsync(c_pw,  ppw,  22 * sizeof(float), 0, cudaMemcpyDeviceToDevice, 0);
    cudaMemcpyToSymbolAsync(c_cnt, pcnt, sizeof(int),        0, cudaMemcpyDeviceToDevice, 0);

    // Slice 0 of the output is the initial state
    cudaMemcpyAsync(out, x, (size_t)npix * sizeof(float), cudaMemcpyDeviceToDevice, 0);

    constexpr int T = 4;
    dim3 blk(32, 8, 1);
    dim3 grd(IMG_W / (32 * 4), IMG_H / (8 * T), B);   // (4, 16, B)

    for (int s = 0; s < steps; ++s) {
        const float* src = out + (size_t)s       * npix;
        float*       dst = out + (size_t)(s + 1) * npix;
        step_kernel<T><<<grd, blk>>>(src, dst);
    }
}